// round 9
// baseline (speedup 1.0000x reference)
#include <cuda_runtime.h>

#define GRID 128
#define TPB  512

// cross-block scratch (allocation-free rule: __device__ globals)
__device__ float g_Cpart[GRID];
__device__ float4 g_upart4[GRID * 32];      // per-block u1[64],u2[64] as 32 float4
struct alignas(128) PadU { unsigned v; unsigned pad[31]; };
__device__ PadU g_cnt;                      // separate 128B lines: arrival RMWs on
__device__ PadU g_gen;                      // cnt don't contend with gen pollers

// Global grid barrier, scoped release/acquire only (no gpu-wide fence, no
// CCTL.IVALL L1D flush). 128 CTAs of 512 threads = a single wave (<=148 SMs),
// so all blocks are co-resident: spin cannot deadlock. Sense-reversal gen
// handles reuse across barriers and graph replays. Integer-only, deterministic.
__device__ __forceinline__ void gridbar() {
    __syncthreads();
    if (threadIdx.x == 0) {
        unsigned* cnt = &g_cnt.v;
        unsigned* gen = &g_gen.v;
        unsigned g;
        asm volatile("ld.relaxed.gpu.global.u32 %0, [%1];" : "=r"(g) : "l"(gen));
        unsigned old;
        asm volatile("atom.acq_rel.gpu.global.add.u32 %0, [%1], %2;"
                     : "=r"(old) : "l"(cnt), "r"(1u) : "memory");
        if (old == GRID - 1) {
            asm volatile("st.relaxed.gpu.global.u32 [%0], %1;" :: "l"(cnt), "r"(0u) : "memory");
            asm volatile("st.release.gpu.global.u32 [%0], %1;" :: "l"(gen), "r"(g + 1) : "memory");
        } else {
            unsigned cur;
            do {
                asm volatile("ld.acquire.gpu.global.u32 %0, [%1];"
                             : "=r"(cur) : "l"(gen) : "memory");
            } while (cur == g);
        }
    }
    __syncthreads();
}

__device__ __forceinline__ float dot4(float4 a, float4 b, float acc) {
    return fmaf(a.x, b.x, fmaf(a.y, b.y, fmaf(a.z, b.z, fmaf(a.w, b.w, acc))));
}
__device__ __forceinline__ float4 ldcg4(const float4* p) {
    float4 v;
    asm volatile("ld.global.cg.v4.f32 {%0,%1,%2,%3}, [%4];"
                 : "=f"(v.x), "=f"(v.y), "=f"(v.z), "=f"(v.w) : "l"(p));
    return v;
}
__device__ __forceinline__ void stcg4(float4* p, float4 v) {
    asm volatile("st.global.cg.v4.f32 [%0], {%1,%2,%3,%4};"
                 :: "l"(p), "f"(v.x), "f"(v.y), "f"(v.z), "f"(v.w) : "memory");
}

__global__ void __launch_bounds__(TPB, 1)
gcn_fused(const float4* __restrict__ x4,
          const float* __restrict__ adj_w,
          const float* __restrict__ adj_b_p,
          const float4* __restrict__ weight4,
          const float4* __restrict__ bias4,
          float* __restrict__ out) {
    const int t     = threadIdx.x;
    const int blk   = blockIdx.x;
    const int batch = blk >> 5;          // 32 blocks (4096 rows) per batch

    __shared__ float sx[128 * 64];       // x tile (32 KB), global-read ONCE
    __shared__ float sW[4096];           // weight, prefetched in phase 1
    __shared__ float sB[64];
    __shared__ float s_sr[128], s_sc[128];
    __shared__ float s_e1[128], s_d[128], s_w2[128];
    __shared__ float red[1024];
    __shared__ float su[128], sT[128];
    __shared__ float ws[16];

    // ---------------- Phase 1: loads + row dots + C partial ----------------
    const float ab = __ldg(adj_b_p);
    {
        const int quad = t & 3;          // 4 lanes per row (16 floats each)
        const int r    = t >> 2;         // 0..127
        const int row  = blk * 128 + r;

        // x tile loads first (critical path)
        const float4* xr = x4 + (size_t)row * 16 + quad * 4;
        float4 v0 = xr[0], v1 = xr[1], v2 = xr[2], v3 = xr[3];

        // prefetch weight + bias into smem (needed only after barrier 2)
        ((float4*)sW)[t]       = weight4[t];
        ((float4*)sW)[512 + t] = weight4[512 + t];
        if (t < 16) ((float4*)sB)[t] = bias4[t];

        const float4* w4 = (const float4*)adj_w;
        float4 wc0 = w4[quad * 4 + 0], wc1 = w4[quad * 4 + 1];
        float4 wc2 = w4[quad * 4 + 2], wc3 = w4[quad * 4 + 3];
        float4 wr0 = w4[16 + quad * 4 + 0], wr1 = w4[16 + quad * 4 + 1];
        float4 wr2 = w4[16 + quad * 4 + 2], wr3 = w4[16 + quad * 4 + 3];

        float4* sxr = (float4*)(sx + r * 64 + quad * 16);
        sxr[0] = v0; sxr[1] = v1; sxr[2] = v2; sxr[3] = v3;

        float sc = dot4(v3, wc3, dot4(v2, wc2, dot4(v1, wc1, dot4(v0, wc0, 0.f))));
        float sr = dot4(v3, wr3, dot4(v2, wr2, dot4(v1, wr1, dot4(v0, wr0, 0.f))));
        sc += __shfl_xor_sync(0xffffffffu, sc, 1);
        sc += __shfl_xor_sync(0xffffffffu, sc, 2);
        sr += __shfl_xor_sync(0xffffffffu, sr, 1);
        sr += __shfl_xor_sync(0xffffffffu, sr, 2);
        if (quad == 0) { s_sr[r] = sr; s_sc[r] = sc; }

        float p = (quad == 0) ? sc : 0.f;
        p += __shfl_xor_sync(0xffffffffu, p, 4);
        p += __shfl_xor_sync(0xffffffffu, p, 8);
        p += __shfl_xor_sync(0xffffffffu, p, 16);
        if ((t & 31) == 0) ws[t >> 5] = p;
        __syncthreads();
        if (t == 0) {
            float s = 0.f;
#pragma unroll
            for (int w = 0; w < 16; w++) s += ws[w];
            __stcg(&g_Cpart[blk], s);
        }
    }
    gridbar();   // barrier 1: C partials in L2

    // ---------------- Phase 2: d per row, u1/u2 partials --------------------
    {
        // Only warps 0-3 need C: redundant per-warp fold, no broadcast sync.
        if (t < 128) {
            float p = __ldcg(&g_Cpart[batch * 32 + (t & 31)]);
            p += __shfl_xor_sync(0xffffffffu, p, 16);
            p += __shfl_xor_sync(0xffffffffu, p, 8);
            p += __shfl_xor_sync(0xffffffffu, p, 4);
            p += __shfl_xor_sync(0xffffffffu, p, 2);
            p += __shfl_xor_sync(0xffffffffu, p, 1);   // C in all lanes
            const float srv = s_sr[t] + ab;
            const float d = rsqrtf(fmaxf(fmaf(4096.f, srv, p), 1.0f));
            s_e1[t] = d * srv;          // output: e1*T1
            s_d[t]  = d;                // output + u1 weight
            s_w2[t] = s_sc[t] * d;      // u2 weight
        }
        __syncthreads();

        const int f   = t & 63;
        const int sub = t >> 6;          // 8 row-lanes
        float a1 = 0.f, a2 = 0.f;
#pragma unroll
        for (int k = 0; k < 16; k++) {
            const int r = sub + (k << 3);
            const float xv = sx[r * 64 + f];
            a1 = fmaf(s_d[r],  xv, a1);
            a2 = fmaf(s_w2[r], xv, a2);
        }
        red[t]       = a1;
        red[512 + t] = a2;
        __syncthreads();
        if (t < 128) {                   // fold both halves in one round
            const int which = t >> 6;    // 0: u1, 1: u2
            const int o     = t & 63;
            const float* rp = red + which * 512 + o;
            float s = 0.f;
#pragma unroll
            for (int k = 0; k < 8; k++) s += rp[64 * k];
            red[t] = s;                  // stage for vector store
        }
        __syncthreads();
        if (t < 32)                      // 32 float4 = u1[64],u2[64]
            stcg4(&g_upart4[blk * 32 + t], ((const float4*)red)[t]);
    }
    gridbar();   // barrier 2: u partials in L2

    // ---------------- Phase 3: fold u, matvec T, stream output -------------
    {
        // fold 32 u-partials (16 KB, L2-hot): 256 threads x 4 vector loads each
        // -> 8 staged groups of 128 floats = 1024 floats (fits red exactly).
        if (t < 256) {
            const int e4 = t & 31;       // float4 index within 128-float record
            const int g8 = t >> 5;       // 8 groups of 4 partials
            const float4* up = &g_upart4[(batch * 32 + g8 * 4) * 32 + e4];
            float4 p0 = ldcg4(up);
            float4 p1 = ldcg4(up + 32);
            float4 p2 = ldcg4(up + 64);
            float4 p3 = ldcg4(up + 96);
            float4 acc;
            acc.x = (p0.x + p1.x) + (p2.x + p3.x);
            acc.y = (p0.y + p1.y) + (p2.y + p3.y);
            acc.z = (p0.z + p1.z) + (p2.z + p3.z);
            acc.w = (p0.w + p1.w) + (p2.w + p3.w);
            ((float4*)red)[t] = acc;     // red[g8*128 + e4*4 .. +3]
        }
        __syncthreads();
        if (t < 128) {
            float s = 0.f;
#pragma unroll
            for (int k = 0; k < 8; k++) s += red[k * 128 + t];
            su[t] = s;
        }
        __syncthreads();

        // split-K matvec: 4 threads per (which,o) pair, 16-FMA chains
        {
            const int pair  = t & 127;
            const int which = pair >> 6, o = pair & 63;
            const int split = t >> 7;            // 0..3
            const float* u = &su[which * 64 + split * 16];
            const float* w = &sW[split * 16 * 64 + o];
            float p = 0.f;
#pragma unroll
            for (int ff = 0; ff < 16; ff++)
                p = fmaf(u[ff], w[ff * 64], p);
            red[t] = p;
        }
        __syncthreads();
        if (t < 128)
            sT[t] = (red[t] + red[128 + t]) + (red[256 + t] + red[384 + t]);
        __syncthreads();

        // output: thread t handles row r, 16 consecutive o's (4 float4 stores)
        const int r = t >> 2, q = t & 3;
        const float e1 = s_e1[r];
        const float dd = s_d[r];
        const float4* T1p = (const float4*)&sT[q * 16];
        const float4* T2p = (const float4*)&sT[64 + q * 16];
        const float4* Bp  = (const float4*)&sB[q * 16];
        float4* op = (float4*)&out[(size_t)((blk * 128 + r) << 6) + q * 16];
#pragma unroll
        for (int i = 0; i < 4; i++) {
            const float4 t1 = T1p[i], t2 = T2p[i], bb = Bp[i];
            float4 v;
            v.x = fmaxf(fmaf(e1, t1.x, fmaf(dd, t2.x, bb.x)), 0.f);
            v.y = fmaxf(fmaf(e1, t1.y, fmaf(dd, t2.y, bb.y)), 0.f);
            v.z = fmaxf(fmaf(e1, t1.z, fmaf(dd, t2.z, bb.z)), 0.f);
            v.w = fmaxf(fmaf(e1, t1.w, fmaf(dd, t2.w, bb.w)), 0.f);
            op[i] = v;
        }
    }
}

extern "C" void kernel_launch(void* const* d_in, const int* in_sizes, int n_in,
                              void* d_out, int out_size) {
    const float* x = nullptr;       // 1048576
    const float* adj_w = nullptr;   // 128
    const float* adj_b = nullptr;   // 1
    const float* weight = nullptr;  // 4096
    const float* bias = nullptr;    // 64
    for (int i = 0; i < n_in; i++) {
        switch (in_sizes[i]) {
            case 1048576: x      = (const float*)d_in[i]; break;
            case 128:     adj_w  = (const float*)d_in[i]; break;
            case 1:       adj_b  = (const float*)d_in[i]; break;
            case 4096:    weight = (const float*)d_in[i]; break;
            case 64:      bias   = (const float*)d_in[i]; break;
            default: break;
        }
    }
    float* out = (float*)d_out;

    gcn_fused<<<GRID, TPB>>>((const float4*)x, adj_w, adj_b,
                             (const float4*)weight, (const float4*)bias, out);
}

// round 10
// speedup vs baseline: 1.1293x; 1.1293x over previous
#include <cuda_runtime.h>

#define GRID 128
#define TPB  512

// cross-block scratch (allocation-free rule: __device__ globals)
__device__ float g_Cpart[GRID];
__device__ float g_upart[GRID * 128];
struct alignas(128) PadU { unsigned v; unsigned pad[31]; };
__device__ PadU g_cnt;                 // separate 128B lines: gen pollers don't
__device__ PadU g_gen;                 // contend with arrival RMWs on cnt

// Global grid barrier, scoped release/acquire (no gpu-wide fence, no CCTL.IVALL).
// 128 CTAs of 512 threads = a single wave (<=148 SMs): co-resident, spin cannot
// deadlock. Sense-reversal gen handles reuse across barriers and graph replays.
__device__ __forceinline__ void gridbar() {
    __syncthreads();
    if (threadIdx.x == 0) {
        unsigned g;
        asm volatile("ld.relaxed.gpu.global.u32 %0, [%1];" : "=r"(g) : "l"(&g_gen.v));
        unsigned old;
        asm volatile("atom.acq_rel.gpu.global.add.u32 %0, [%1], %2;"
                     : "=r"(old) : "l"(&g_cnt.v), "r"(1u) : "memory");
        if (old == GRID - 1) {
            asm volatile("st.relaxed.gpu.global.u32 [%0], %1;" :: "l"(&g_cnt.v), "r"(0u) : "memory");
            asm volatile("st.release.gpu.global.u32 [%0], %1;" :: "l"(&g_gen.v), "r"(g + 1) : "memory");
        } else {
            unsigned cur;
            do {
                asm volatile("ld.acquire.gpu.global.u32 %0, [%1];"
                             : "=r"(cur) : "l"(&g_gen.v) : "memory");
            } while (cur == g);
        }
    }
    __syncthreads();
}

__device__ __forceinline__ float dot4(float4 a, float4 b, float acc) {
    return fmaf(a.x, b.x, fmaf(a.y, b.y, fmaf(a.z, b.z, fmaf(a.w, b.w, acc))));
}

__global__ void __launch_bounds__(TPB, 1)
gcn_fused(const float4* __restrict__ x4,
          const float* __restrict__ adj_w,
          const float* __restrict__ adj_b_p,
          const float4* __restrict__ weight4,
          const float4* __restrict__ bias4,
          float* __restrict__ out) {
    const int t     = threadIdx.x;
    const int blk   = blockIdx.x;
    const int batch = blk >> 5;          // 32 blocks (4096 rows) per batch

    __shared__ float sx[128 * 64];       // this block's x tile (32 KB), read ONCE
    __shared__ float sW[4096];           // weight (prefetched AFTER C store)
    __shared__ float sB[64];
    __shared__ float s_sr[128];
    __shared__ float s_sc[128];
    __shared__ float red[1024];
    __shared__ float sT[128];
    __shared__ float ws[16];
    __shared__ float sCsh;

    // ---------- Phase 1: load x tile -> smem, row dots, C partial ----------
    {
        const int quad = t & 3;          // 4 lanes per row (16 floats each)
        const int r    = t >> 2;         // 0..127
        const int row  = blk * 128 + r;

        const float4* w4 = (const float4*)adj_w;
        float4 wc0 = w4[quad * 4 + 0], wc1 = w4[quad * 4 + 1];
        float4 wc2 = w4[quad * 4 + 2], wc3 = w4[quad * 4 + 3];
        float4 wr0 = w4[16 + quad * 4 + 0], wr1 = w4[16 + quad * 4 + 1];
        float4 wr2 = w4[16 + quad * 4 + 2], wr3 = w4[16 + quad * 4 + 3];

        const float4* xr = x4 + (size_t)row * 16 + quad * 4;
        float4 v0 = xr[0], v1 = xr[1], v2 = xr[2], v3 = xr[3];

        float4* sxr = (float4*)(sx + r * 64 + quad * 16);
        sxr[0] = v0; sxr[1] = v1; sxr[2] = v2; sxr[3] = v3;

        float sc = dot4(v3, wc3, dot4(v2, wc2, dot4(v1, wc1, dot4(v0, wc0, 0.f))));
        float sr = dot4(v3, wr3, dot4(v2, wr2, dot4(v1, wr1, dot4(v0, wr0, 0.f))));
        sc += __shfl_xor_sync(0xffffffffu, sc, 1);
        sc += __shfl_xor_sync(0xffffffffu, sc, 2);
        sr += __shfl_xor_sync(0xffffffffu, sr, 1);
        sr += __shfl_xor_sync(0xffffffffu, sr, 2);

        if (quad == 0) { s_sr[r] = sr; s_sc[r] = sc; }

        float p = (quad == 0) ? sc : 0.f;
        p += __shfl_xor_sync(0xffffffffu, p, 4);
        p += __shfl_xor_sync(0xffffffffu, p, 8);
        p += __shfl_xor_sync(0xffffffffu, p, 16);
        if ((t & 31) == 0) ws[t >> 5] = p;
        __syncthreads();
        if (t == 0) {
            float s = 0.f;
#pragma unroll
            for (int w = 0; w < 16; w++) s += ws[w];
            __stcg(&g_Cpart[blk], s);
        }
        // weight/bias prefetch AFTER the barrier-feeding store: overlaps the
        // barrier wait, adds nothing to the grid-amplified critical path.
        ((float4*)sW)[t]       = weight4[t];
        ((float4*)sW)[512 + t] = weight4[512 + t];
        if (t < 16) ((float4*)sB)[t] = bias4[t];
    }
    gridbar();   // barrier 1: C partials visible in L2

    // ---------- Phase 2: fold C, u1/u2 partials (x from smem) --------------
    float C, ab;
    {
        if (t < 32) {                    // per-batch C fold (32 partials)
            float p = __ldcg(&g_Cpart[batch * 32 + t]);
            p += __shfl_xor_sync(0xffffffffu, p, 16);
            p += __shfl_xor_sync(0xffffffffu, p, 8);
            p += __shfl_xor_sync(0xffffffffu, p, 4);
            p += __shfl_xor_sync(0xffffffffu, p, 2);
            p += __shfl_xor_sync(0xffffffffu, p, 1);
            if (t == 0) sCsh = p;
        }
        __syncthreads();
        C  = sCsh;
        ab = __ldg(adj_b_p);

        const int f   = t & 63;
        const int sub = t >> 6;          // 8 row-lanes
        float a1 = 0.f, a2 = 0.f;
#pragma unroll
        for (int k = 0; k < 16; k++) {
            const int r = sub + (k << 3);
            const float srv = s_sr[r];
            const float scv = s_sc[r];
            const float d = rsqrtf(fmaxf(fmaf(4096.f, srv + ab, C), 1.0f));
            const float xv = sx[r * 64 + f];
            a1 = fmaf(d, xv, a1);
            a2 = fmaf(scv * d, xv, a2);
        }
        red[t] = a1;
        red[512 + t] = a2;
        __syncthreads();
        if (t < 64) {
            float s1 = 0.f, s2 = 0.f;
#pragma unroll
            for (int k = 0; k < 8; k++) {
                s1 += red[t + 64 * k];
                s2 += red[512 + t + 64 * k];
            }
            __stcg(&g_upart[blk * 128 + t],      s1);
            __stcg(&g_upart[blk * 128 + 64 + t], s2);
        }
    }
    gridbar();   // barrier 2: u partials visible in L2

    // ---------- Phase 3: every block folds u + matvec T, streams output ----
    {
        // fold 32 u-partials of this batch: 4096 floats, 8 ldcg per thread
        const int e  = t & 127;
        const int g4 = t >> 7;           // 4 groups of 8 partials
        float acc = 0.f;
#pragma unroll
        for (int k = 0; k < 8; k++)
            acc += __ldcg(&g_upart[(batch * 32 + g4 * 8 + k) * 128 + e]);
        red[t] = acc;
        __syncthreads();
        if (t < 128) {
            const float u = red[t] + red[128 + t] + red[256 + t] + red[384 + t];
            red[512 + t] = u;
        }
        __syncthreads();
        if (t < 128) {                   // T[which][o] = sum_f u[which][f] * W[f][o]
            const int which = t >> 6, o = t & 63;
            const float* u = &red[512 + which * 64];
            float acc2 = 0.f;
#pragma unroll
            for (int ff = 0; ff < 64; ff++)
                acc2 = fmaf(u[ff], sW[ff * 64 + o], acc2);
            sT[t] = acc2;
        }
        __syncthreads();

        const int o   = t & 63;
        const int sub = t >> 6;
        const float T1 = sT[o];
        const float T2 = sT[64 + o];
        const float bv = sB[o];
#pragma unroll
        for (int k = 0; k < 16; k++) {
            const int r = sub + (k << 3);
            const float srv = s_sr[r] + ab;
            const float d = rsqrtf(fmaxf(fmaf(4096.f, srv, C), 1.0f));
            const float v = d * fmaf(srv, T1, T2) + bv;
            out[(size_t)((blk * 128 + r) << 6) + o] = fmaxf(v, 0.f);
        }
    }
}

extern "C" void kernel_launch(void* const* d_in, const int* in_sizes, int n_in,
                              void* d_out, int out_size) {
    const float* x = nullptr;       // 1048576
    const float* adj_w = nullptr;   // 128
    const float* adj_b = nullptr;   // 1
    const float* weight = nullptr;  // 4096
    const float* bias = nullptr;    // 64
    for (int i = 0; i < n_in; i++) {
        switch (in_sizes[i]) {
            case 1048576: x      = (const float*)d_in[i]; break;
            case 128:     adj_w  = (const float*)d_in[i]; break;
            case 1:       adj_b  = (const float*)d_in[i]; break;
            case 4096:    weight = (const float*)d_in[i]; break;
            case 64:      bias   = (const float*)d_in[i]; break;
            default: break;
        }
    }
    float* out = (float*)d_out;

    gcn_fused<<<GRID, TPB>>>((const float4*)x, adj_w, adj_b,
                             (const float4*)weight, (const float4*)bias, out);
}